// round 11
// baseline (speedup 1.0000x reference)
#include <cuda_runtime.h>
#include <cuda_bf16.h>

// VEGAS adaptive-map transform.
// Inputs: y [B,16] f32, grid [16,ninc+1] f32, inc [16,ninc] f32, ninc i32
// Output: x [B,16] f32 followed by jac [B] f32.
//
// LSU-serialization-bound design (validated R9):
//  - lane-per-quarter layout: all LDG.128/STG.128 fully coalesced.
//  - ONE LDS.64 per dim from interleaved float2 {g,h} fp32 table (exact).
//  - Table layout [j][iy][q]: element (d=q*4+j, iy) at ((j*ninc+iy)<<2)+q.
//    bank-pair = 4*(iy&3)+q -> each quarter owns 4 private bank-pairs
//    (same conflict property as R8 mapping) but address = ONE IMAD.
//  - Magic-number floor: u=__fadd_rz(t,2^23) (trunc toward 0 == floor, t>=0),
//    iy=mantissa bits, fiy=u-2^23 exact, dy=t-fiy. Removes F2I/I2F (~20cyc
//    cvt ops) from the chain. Float-side clamp u=min(u,2^23+ninc-1) keeps
//    iy/fiy consistent and yields dy=1 at t=ninc -> exact right edge.
//  - streaming cache hints on the 128MB y/x/jac streams.
//  - 1024 thr, 1 CTA/SM, 2 groups/iter depth-1 prefetch.

__global__ void __launch_bounds__(1024, 1) vegas_map_d16_kernel(
    const float4* __restrict__ y4,
    const float* __restrict__ grd,
    const float* __restrict__ inc,
    float4* __restrict__ x4,
    float* __restrict__ jac,
    int G,            // B*4 float4 groups
    int ninc, int kfull)
{
    extern __shared__ float2 tab[];        // [4 j][ninc iy][4 q]
    const int tabN = 16 * ninc;

    // Build: iterate destination-linear (coalesced STS).
    // a = ((j*ninc + iy)<<2) + q  ->  q=a&3, jy=a>>2, j=jy/ninc, iy=jy%ninc
    for (int a = threadIdx.x; a < tabN; a += blockDim.x) {
        const int q  = a & 3;
        const int jy = a >> 2;
        const int j  = jy / ninc;
        const int iy = jy - j * ninc;
        const int d  = q * 4 + j;
        tab[a] = make_float2(grd[d * (ninc + 1) + iy],
                             inc[d * ninc + iy]);
    }
    __syncthreads();

    const float MAGIC  = 8388608.0f;               // 2^23
    const float nincf  = (float)ninc;
    const float nincf4 = (nincf * nincf) * (nincf * nincf);
    const float umax   = MAGIC + (float)(ninc - 1);
    const int   T      = gridDim.x * blockDim.x;   // total threads (mult of 4)
    const int   lane   = threadIdx.x & 31;
    const int   g0     = blockIdx.x * blockDim.x + threadIdx.x;

    // quarter (g&3) invariant across iterations (T is a multiple of 4)
    const int q = g0 & 3;
    // hoisted per-j base addresses: base_j = ((j*ninc)<<2) + q
    const int base0 = q;
    const int base1 = (ninc << 2) + q;
    const int base2 = (ninc << 3) + q;
    const int base3 = (ninc << 3) + (ninc << 2) + q;

    #define DIM(VY, BASE, XS)                                                  \
    {                                                                          \
        const float t  = (VY) * nincf;                                         \
        float u = __fadd_rz(t, MAGIC);          /* floor via trunc */          \
        u = fminf(u, umax);                     /* clamp to ninc-1 */          \
        const int   iy  = __float_as_int(u) & 0x007FFFFF;                      \
        const float fiy = u - MAGIC;            /* exact (float)iy */          \
        const float dy  = t - fiy;              /* ==1 at t==ninc */           \
        const float2 gh = tab[(BASE) + (iy << 2)];                             \
        (XS) = fmaf(gh.y, dy, gh.x);                                           \
        ph *= gh.y;                                                            \
    }

    #define PROCESS(YV, GIDX)                                                  \
    {                                                                          \
        float xs0, xs1, xs2, xs3;                                              \
        float ph = 1.0f;                                                       \
        DIM((YV).x, base0, xs0)                                                \
        DIM((YV).y, base1, xs1)                                                \
        DIM((YV).z, base2, xs2)                                                \
        DIM((YV).w, base3, xs3)                                                \
        ph *= nincf4;                                                          \
        __stcs(&x4[(GIDX)], make_float4(xs0, xs1, xs2, xs3));                  \
        ph *= __shfl_xor_sync(0xffffffffu, ph, 1);                             \
        ph *= __shfl_xor_sync(0xffffffffu, ph, 2);                             \
        if ((lane & 3) == 0) __stcs(&jac[(GIDX) >> 2], ph);                    \
    }

    float4 curA, curB, nxtA, nxtB;
    int g = g0;

    if (kfull > 0) {
        curA = __ldcs(&y4[g]);
        curB = __ldcs(&y4[g + T]);
        for (int k = 0; k < kfull; ++k) {
            const int gn = g + 2 * T;
            if (k + 1 < kfull) {               // depth-1 prefetch
                nxtA = __ldcs(&y4[gn]);
                nxtB = __ldcs(&y4[gn + T]);
            }
            PROCESS(curA, g)
            PROCESS(curB, g + T)
            curA = nxtA;
            curB = nxtB;
            g = gn;
        }
    }

    // guarded tail (< 2T groups remain)
    if (g < G)     { float4 yv = __ldcs(&y4[g]);     PROCESS(yv, g)     }
    if (g + T < G) { float4 yv = __ldcs(&y4[g + T]); PROCESS(yv, g + T) }

    #undef PROCESS
    #undef DIM
}

// Generic fallback (any D, any ninc): one thread per sample, global tables.
__global__ void vegas_map_generic_kernel(
    const float* __restrict__ y,
    const float* __restrict__ grd,
    const float* __restrict__ inc,
    float* __restrict__ xout,
    float* __restrict__ jac,
    int B, int D, int ninc)
{
    int b = blockIdx.x * blockDim.x + threadIdx.x;
    if (b >= B) return;
    const float nincf = (float)ninc;
    float p = 1.0f;
    for (int d = 0; d < D; ++d) {
        float t  = y[(size_t)b * D + d] * nincf;
        int   iy = (int)t;
        if (iy > ninc) iy = ninc;
        const bool valid = iy < ninc;
        const float dy   = t - (float)iy;
        const int iyi    = valid ? iy : (ninc - 1);
        const float gv = grd[d * (ninc + 1) + iy];
        const float hv = inc[d * ninc + iyi];
        xout[(size_t)b * D + d] = valid ? fmaf(hv, dy, gv) : gv;
        p *= hv * nincf;
    }
    jac[b] = p;
}

extern "C" void kernel_launch(void* const* d_in, const int* in_sizes, int n_in,
                              void* d_out, int out_size)
{
    const float* y   = (const float*)d_in[0];
    const float* grd = (const float*)d_in[1];
    const float* inc = (const float*)d_in[2];

    const int n_y = in_sizes[0];
    const int n_g = in_sizes[1];
    const int n_i = in_sizes[2];

    const int D    = n_g - n_i;          // D*(ninc+1) - D*ninc
    const int ninc = n_i / D;
    const int B    = n_y / D;

    float* x   = (float*)d_out;
    float* jac = x + (size_t)n_y;

    const size_t smem = (size_t)(16 * ninc) * sizeof(float2);

    if (D == 16 && smem <= 200 * 1024 && ninc < (1 << 22)) {
        cudaFuncSetAttribute(vegas_map_d16_kernel,
                             cudaFuncAttributeMaxDynamicSharedMemorySize,
                             (int)smem);
        int dev = 0;
        cudaGetDevice(&dev);
        int sms = 148;
        cudaDeviceGetAttribute(&sms, cudaDevAttrMultiProcessorCount, dev);

        const int threads = 1024;
        const int nCTA    = sms;                 // one wave, 1 CTA/SM
        const int T       = nCTA * threads;
        const int G       = B * 4;               // float4 groups
        const int kfull   = G / (2 * T);         // unguarded iterations

        vegas_map_d16_kernel<<<nCTA, threads, smem>>>(
            (const float4*)y, grd, inc, (float4*)x, jac, G, ninc, kfull);
    } else {
        const int threads = 256;
        const int blocks  = (B + threads - 1) / threads;
        vegas_map_generic_kernel<<<blocks, threads>>>(
            y, grd, inc, x, jac, B, D, ninc);
    }
}